// round 16
// baseline (speedup 1.0000x reference)
#include <cuda_runtime.h>
#include <cuda_bf16.h>

// ---------------- problem constants ----------------
#define H_IMG   2048
#define W_IMG   2048
#define C_IMG   3
#define RAD     5
#define NITER   10
#define PH      (H_IMG + 2*RAD)   // 2058
#define PW      (W_IMG + 2*RAD)   // 2058

// Guarded buffer layout: interior pixel (y,x) lives at row y+GY, col x+GX.
// Guard bands are NEVER written by any kernel (all stores are interior-only),
// and __device__ globals are zero-initialized at module load -> guards are
// permanently zero. Mid iterations therefore load float4 with NO bounds checks.
#define GY      8
#define GX      8
#define PROWS   2104
#define PITCH   2208
#define PLANE   (PROWS * PITCH)
#define BUFSZ   (C_IMG * PLANE)

__device__ float g_U[2][BUFSZ];

// ---------------- packed f32x2 helpers (sm_103a; PTX-only ops) ----------------
typedef unsigned long long u64v2;

#define PACK2(out, lo, hi) \
    asm("mov.b64 %0, {%1, %2};" : "=l"(out) : "f"(lo), "f"(hi))
#define UNPACK2(lo, hi, in) \
    asm("mov.b64 {%0, %1}, %2;" : "=f"(lo), "=f"(hi) : "l"(in))
#define ADD2(out, a, b) \
    asm("add.rn.f32x2 %0, %1, %2;" : "=l"(out) : "l"(a), "l"(b))
#define FMA2(out, a, b, c) \
    asm("fma.rn.f32x2 %0, %1, %2, %3;" : "=l"(out) : "l"(a), "l"(b), "l"(c))

// ---------------- one side-window iteration (3 modes) ----------------
#define TH 44
#define TROWS (TH + 2*RAD)        // 54
#define TW 128
#define TCOLS 148                 // 37 float4; bank-friendly stride
#define TC4   (TCOLS/4)           // 37
#define NF4   (TROWS * TC4)       // 1998
#define H6W   138

#define MODE_FIRST 0
#define MODE_MID   1
#define MODE_LAST  2

// Stage-3 vertical walk with lead sums; (L,R) lanes packed as f32x2.
// FULL=true: every row stores (only xok checked). Otherwise rows [lo,hi) store.
template<bool FULL>
__device__ __forceinline__ void walk(const float* __restrict__ hp,
                                     const float* __restrict__ hp5,
                                     const float* __restrict__ cp,
                                     float* __restrict__ ptr, int stride,
                                     int base, bool xok, int lo, int hi)
{
    const float i36 = 1.0f / 36.0f;
    const float i66 = 1.0f / 66.0f;
    u64v2 I36x2, I66x2, NEG1x2;
    PACK2(I36x2, i36, i36);
    PACK2(I66x2, i66, i66);
    {
        const float m1 = -1.0f;
        PACK2(NEG1x2, m1, m1);
    }

    // ring: rH[j] = {HL,HR} packed; rCc scalar center column
    u64v2 rH[7];
    float rCc[7];
    #pragma unroll
    for (int j = 0; j < 7; j++) {
        int row = base + j;
        float nHL = hp[row * H6W];
        float nHR = hp5[row * H6W];
        u64v2 nH; PACK2(nH, nHL, nHR);
        rH[j] = nH;
        rCc[j] = cp[row * TCOLS];
    }

    // lead sums at j=5: AB = {A,B}
    u64v2 AB;
    {
        u64v2 t01, t23, t45;
        ADD2(t01, rH[0], rH[1]);
        ADD2(t23, rH[2], rH[3]);
        ADD2(t45, rH[4], rH[5]);
        ADD2(t01, t01, t23);
        ADD2(AB, t01, t45);
    }
    float C6 = rCc[0] + rCc[1] + rCc[2] + rCc[3] + rCc[4] + rCc[5];
    float a_, b_;
    UNPACK2(a_, b_, AB);
    float Dw = a_ + b_ - C6;

    u64v2 ABh[6];
    float Dh[6];
    ABh[5] = AB; Dh[5] = Dw;

    // prologue j=6 (row already in ring)
    {
        u64v2 d; FMA2(d, rH[0], NEG1x2, rH[6]);   // rH6 - rH0
        ADD2(AB, AB, d);
    }
    C6 += rCc[6] - rCc[0];
    UNPACK2(a_, b_, AB);
    Dw = a_ + b_ - C6;
    ABh[0] = AB; Dh[0] = Dw;

    // prologue j=7..9
    #pragma unroll
    for (int j = 7; j <= 9; j++) {
        int row = base + j;
        float nHL = hp[row * H6W];
        float nHR = hp5[row * H6W];
        float nCc = cp[row * TCOLS];
        u64v2 nH; PACK2(nH, nHL, nHR);
        u64v2 d; FMA2(d, rH[(j - 6) % 7], NEG1x2, nH);
        ADD2(AB, AB, d);
        C6 += nCc - rCc[(j - 6) % 7];
        rH[j % 7] = nH; rCc[j % 7] = nCc;
        UNPACK2(a_, b_, AB);
        Dw = a_ + b_ - C6;
        ABh[j % 6] = AB; Dh[j % 6] = Dw;
    }

    // main walk: ly = 0..TH/2-1, lead j = 10+ly
    #pragma unroll
    for (int ly = 0; ly < TH / 2; ly++) {
        const int j = 10 + ly;
        {
            int row = base + j;
            float nHL = hp[row * H6W];
            float nHR = hp5[row * H6W];
            float nCc = cp[row * TCOLS];
            u64v2 nH; PACK2(nH, nHL, nHR);
            u64v2 d; FMA2(d, rH[(j - 6) % 7], NEG1x2, nH);
            ADD2(AB, AB, d);
            C6 += nCc - rCc[(j - 6) % 7];
            rH[j % 7] = nH; rCc[j % 7] = nCc;
            UNPACK2(a_, b_, AB);
            Dw = a_ + b_ - C6;
        }

        const u64v2 uAB = ABh[(j - 5) % 6];      // {uL,uR}
        const float uF  = Dh[(j - 5) % 6];
        ABh[j % 6] = AB; Dh[j % 6] = Dw;

        const u64v2 hH = rH[(j - 5) % 7];        // {hL,hR}
        const float c0 = rCc[(j - 5) % 7];
        const float nc0 = -c0;
        u64v2 nc0x2; PACK2(nc0x2, nc0, nc0);

        u64v2 sAB; ADD2(sAB, uAB, AB);           // {uL+A, uR+B}
        u64v2 fLR; FMA2(fLR, hH, NEG1x2, sAB);   // {fL, fR}

        // deltas, reference order [LL,LR,RL,RR,L*k,R*k,k*L,k*R]
        u64v2 d01, d23, d67;
        FMA2(d01, uAB, I36x2, nc0x2);            // d0,d1
        FMA2(d23, AB,  I36x2, nc0x2);            // d2,d3
        FMA2(d67, fLR, I66x2, nc0x2);            // d6,d7
        const float d4 = fmaf(uF, i66, nc0);
        const float d5 = fmaf(Dw, i66, nc0);

        float d0, d1, d2, d3, d6, d7;
        UNPACK2(d0, d1, d01);
        UNPACK2(d2, d3, d23);
        UNPACK2(d6, d7, d67);

        // Tournament argmin, first-min-on-tie; |.| free on FSETP operands.
        const float w01 = (fabsf(d1) < fabsf(d0)) ? d1 : d0;
        const float w23 = (fabsf(d3) < fabsf(d2)) ? d3 : d2;
        const float w45 = (fabsf(d5) < fabsf(d4)) ? d5 : d4;
        const float w67 = (fabsf(d7) < fabsf(d6)) ? d7 : d6;
        const float w03 = (fabsf(w23) < fabsf(w01)) ? w23 : w01;
        const float w47 = (fabsf(w67) < fabsf(w45)) ? w67 : w45;
        const float bd  = (fabsf(w47) < fabsf(w03)) ? w47 : w03;

        if (FULL) {
            if (xok) ptr[ly * stride] = c0 + bd;
        } else {
            if (xok && ly >= lo && ly < hi) ptr[ly * stride] = c0 + bd;
        }
    }
}

template<int MODE>
__global__ __launch_bounds__(256)
void swf_iter(const float* __restrict__ img, float* __restrict__ out, int s) {
    float* __restrict__ Dst = (MODE == MODE_FIRST) ? g_U[0] : g_U[s ^ 1];

    __shared__ float tile[TROWS * TCOLS];   // 54*148 floats = 31.2KB
    __shared__ float h6[TROWS * H6W];       // 54*138 floats = 29.1KB

    const int c  = blockIdx.z;
    const int x0 = blockIdx.x * TW;
    const int y0 = blockIdx.y * TH;
    const int t  = threadIdx.x;             // 0..255
    float* __restrict__ Dp = Dst + c * PLANE;

    // ---- Stage 1 ----
    if (MODE == MODE_FIRST) {
        // Gather directly from HWC img with edge replicate; zero outside the
        // padded field. Scalar + clamped, paid only on iteration 0.
        for (int idx = t; idx < TROWS * TCOLS; idx += 256) {
            int r   = idx / TCOLS;
            int lxc = idx - r * TCOLS;
            int y = y0 + r - 5;             // padded-field row
            int x = x0 + lxc - 8;           // padded-field col
            float v = 0.0f;
            if (y >= 0 && y < PH && x >= 0 && x < PW) {
                int sy = y - RAD; sy = sy < 0 ? 0 : (sy > H_IMG - 1 ? H_IMG - 1 : sy);
                int sx = x - RAD; sx = sx < 0 ? 0 : (sx > W_IMG - 1 ? W_IMG - 1 : sx);
                v = img[(sy * W_IMG + sx) * C_IMG + c];
            }
            tile[idx] = v;
        }
    } else {
        // Unconditional float4 tile load (guards supply zeros).
        // Independent per-k address computation: all LDGs issue back-to-back.
        const float* __restrict__ Sp = g_U[s] + c * PLANE;
        const float4* __restrict__ Sp4 =
            (const float4*)(Sp + (y0 + 3) * PITCH + x0);
        float4* tile4 = (float4*)tile;
        #pragma unroll
        for (int k = 0; k < 8; k++) {
            int idx = t + k * 256;
            if (idx < NF4) {
                int r  = idx / TC4;
                int c4 = idx - r * TC4;
                tile4[r * TC4 + c4] = Sp4[r * (PITCH / 4) + c4];
            }
        }
    }
    __syncthreads();

    // ---- Stage 2: horizontal extended 6-sums; 4 segs x 34 cols per row,
    //      float2-paired LDS/STS (all accesses 8B-aligned: strides 148/138 even,
    //      seg starts even). h6[r][cc] = sum tile[r][cc+3 .. cc+8].
    if (t < TROWS * 4) {
        int r   = t >> 2;
        int seg = t & 3;
        int sx  = seg * 34;                  // 0,34,68,102; writes cc in [sx,sx+34)
        const float* trow = &tile[r * TCOLS + sx];
        float* hrow = &h6[r * H6W + sx];
        const float2* tp = (const float2*)(trow + 2);  // tp[k]=(trow[2+2k],trow[3+2k])
        float2* hq = (float2*)hrow;

        float2 p0 = tp[0];   // t2,t3
        float2 p1 = tp[1];   // t4,t5
        float2 p2 = tp[2];   // t6,t7
        float2 p3 = tp[3];   // t8,t9
        float e[6] = {p0.y, p1.x, p1.y, p2.x, p2.y, p3.x};   // t3..t8
        float sum = p0.y + p1.x + p1.y + p2.x + p2.y + p3.x;
        float2 ob;
        ob.x = sum;                          // h[0] = t3+..+t8
        sum += p3.y - e[0];                  // step 1: +t9 -t3
        e[0] = p3.y;
        ob.y = sum;
        hq[0] = ob;
        #pragma unroll
        for (int i = 2; i < 34; i += 2) {
            float2 nl = tp[(i + 6) >> 1];    // (trow[i+8], trow[i+9])
            sum += nl.x - e[(i - 1) % 6];
            e[(i - 1) % 6] = nl.x;
            ob.x = sum;
            sum += nl.y - e[i % 6];
            e[i % 6] = nl.y;
            ob.y = sum;
            hq[i >> 1] = ob;
        }
    }
    __syncthreads();

    // ---- Stage 3 ----
    const int lx   = t & 127;
    const int half = t >> 7;
    const int base = half * (TH / 2);        // 0 or 22
    const int gx   = x0 + lx;

    const float* hp  = h6 + lx;
    const float* hp5 = h6 + lx + 5;
    const float* cp  = tile + lx + 8;

    const int row0 = y0 + base;              // first output row (padded field)

    if (MODE == MODE_LAST) {
        // Write cropped HWC output directly: valid gy,gx in [5, 2052].
        const bool xok = (gx >= RAD) && (gx < PW - RAD);
        int lo = RAD - row0;        if (lo < 0) lo = 0;
        int hi = (PH - RAD) - row0; if (hi > TH / 2) hi = TH / 2;
        float* optr = out + (((row0 - RAD) * W_IMG) + (gx - RAD)) * C_IMG + c;
        walk<false>(hp, hp5, cp, optr, W_IMG * C_IMG, base, xok, lo, hi);
    } else {
        const bool xok = (gx < PW);
        float* Drow = Dp + (row0 + GY) * PITCH + gx + GX;
        if (row0 + TH / 2 <= PH) {
            walk<true>(hp, hp5, cp, Drow, PITCH, base, xok, 0, TH / 2);
        } else {
            int nvalid = PH - row0;
            walk<false>(hp, hp5, cp, Drow, PITCH, base, xok, 0, nvalid);
        }
    }
}

extern "C" void kernel_launch(void* const* d_in, const int* in_sizes, int n_in,
                              void* d_out, int out_size) {
    const float* img = (const float*)d_in[0];   // (2048,2048,3) f32; d_in[1] hardcoded
    float* out = (float*)d_out;

    dim3 block(256, 1, 1);
    dim3 grid((PW + TW - 1) / TW, (PH + TH - 1) / TH, C_IMG);

    // iter 0: img -> g_U[0]
    swf_iter<MODE_FIRST><<<grid, block>>>(img, out, 0);
    // iters 1..8: g_U[(i-1)&1] -> g_U[i&1]
    for (int i = 1; i <= 8; i++) {
        swf_iter<MODE_MID><<<grid, block>>>(img, out, (i - 1) & 1);
    }
    // iter 9: g_U[0] -> out (cropped HWC)
    swf_iter<MODE_LAST><<<grid, block>>>(img, out, 0);
}